// round 17
// baseline (speedup 1.0000x reference)
#include <cuda_runtime.h>
#include <cuda_bf16.h>
#include <math.h>

#define D 256
#define K 5
#define THREADS 256
#define MIN_BLOCKS_PER_SM 5
#define BLOCKS 740                     // 148 SMs * 5 resident blocks = exactly one wave
#define WARPS_PER_BLOCK (THREADS / 32)
#define TOTAL_WARPS (BLOCKS * WARPS_PER_BLOCK)

// Lock-free global top-5 (static device globals -- zero-initialized, no allocation)
__device__ unsigned long long g_top5[K];
__device__ unsigned int g_done = 0;

// tie-break matches jax top_k: higher value first; equal value -> lower index first
__device__ __forceinline__ bool better(float v, int i, float V, int I) {
    return (v > V) || (v == V && i < I);
}

__device__ __forceinline__ void insert_top5(float v, int i, float tv[K], int ti[K]) {
    if (!better(v, i, tv[K - 1], ti[K - 1])) return;
    tv[K - 1] = v; ti[K - 1] = i;
#pragma unroll
    for (int j = K - 1; j > 0; --j) {
        if (better(tv[j], ti[j], tv[j - 1], ti[j - 1])) {
            float fv = tv[j]; tv[j] = tv[j - 1]; tv[j - 1] = fv;
            int   fi = ti[j]; ti[j] = ti[j - 1]; ti[j - 1] = fi;
        }
    }
}

// pack (value, idx) into one sortable u64: bigger key = better candidate.
// high 32: monotonic float transform; low 32: ~idx (smaller idx -> larger key).
__device__ __forceinline__ unsigned long long pack_key(float v, int idx) {
    unsigned int b = __float_as_uint(v);
    b = (b & 0x80000000u) ? ~b : (b | 0x80000000u);
    return ((unsigned long long)b << 32) | (unsigned long long)(~(unsigned int)idx);
}

// -------- Single fused kernel: norm + scan + block top-5 + atomic merge + tail ------
__global__ void __launch_bounds__(THREADS, MIN_BLOCKS_PER_SM)
knn_scan(const float* __restrict__ q, const float* __restrict__ emb, int n,
         float* __restrict__ out) {
    __shared__ float s_q[D];
    __shared__ float s_part[WARPS_PER_BLOCK];
    __shared__ float s_norm;
    __shared__ float mv[THREADS * K];
    __shared__ int   mi[THREADS * K];
    __shared__ bool  s_last;

    const int t    = threadIdx.x;
    const int lane = t & 31;

    // --- normalize query into smem (per block; L2-resident after first block) ---
    {
        float v = q[t];
        float sq = v * v;
#pragma unroll
        for (int off = 16; off > 0; off >>= 1)
            sq += __shfl_down_sync(0xffffffffu, sq, off);
        if (lane == 0) s_part[t >> 5] = sq;
        __syncthreads();
        if (t == 0) {
            float tot = 0.f;
#pragma unroll
            for (int i = 0; i < WARPS_PER_BLOCK; ++i) tot += s_part[i];
            s_norm = fmaxf(sqrtf(tot), 1e-12f);
        }
        __syncthreads();
        s_q[t] = v / s_norm;
        __syncthreads();
    }

    const float4* sq4 = (const float4*)s_q;
    const float4 q0 = sq4[lane];
    const float4 q1 = sq4[lane + 32];

    float tv[K]; int ti[K];
#pragma unroll
    for (int j = 0; j < K; ++j) { tv[j] = -INFINITY; ti[j] = 0x7fffffff; }

    const int warp = (blockIdx.x * THREADS + t) >> 5;
    const int chunk = (n + TOTAL_WARPS - 1) / TOTAL_WARPS;
    int rbeg = warp * chunk;
    int rend = rbeg + chunk; if (rend > n) rend = n;
    if (rbeg > n) rbeg = n;

    const bool h16 = (lane & 16) != 0;
    const bool h8  = (lane & 8)  != 0;
    const int r_off = (h16 ? 1 : 0) + (h8 ? 2 : 0);
    const bool do_ins = (lane & 7) == 0;

    int row = rbeg;
    for (; row + 4 <= rend; row += 4) {
        float4 A[4], B[4];
#pragma unroll
        for (int r = 0; r < 4; ++r) {
            const float4* e = (const float4*)(emb + (size_t)(row + r) * D);
            A[r] = e[lane];
            B[r] = e[lane + 32];
        }
        float d[4];
#pragma unroll
        for (int r = 0; r < 4; ++r) {
            float s = fmaf(A[r].x, q0.x, fmaf(A[r].y, q0.y, fmaf(A[r].z, q0.z, A[r].w * q0.w)));
            d[r] = fmaf(B[r].x, q1.x, fmaf(B[r].y, q1.y, fmaf(B[r].z, q1.z, fmaf(B[r].w, q1.w, s))));
        }
        // 4-way warp reduce in 5 shuffles:
        float send01 = h16 ? d[0] : d[1];
        float s01 = (h16 ? d[1] : d[0]) + __shfl_xor_sync(0xffffffffu, send01, 16);
        float send23 = h16 ? d[2] : d[3];
        float s23 = (h16 ? d[3] : d[2]) + __shfl_xor_sync(0xffffffffu, send23, 16);
        float send = h8 ? s01 : s23;
        float s = (h8 ? s23 : s01) + __shfl_xor_sync(0xffffffffu, send, 8);
        s += __shfl_xor_sync(0xffffffffu, s, 4);
        s += __shfl_xor_sync(0xffffffffu, s, 2);
        s += __shfl_xor_sync(0xffffffffu, s, 1);
        // lanes 0,8,16,24 hold totals of rows row+0, row+2, row+1, row+3
        if (do_ins) insert_top5(s, row + r_off, tv, ti);
    }
    // remainder rows (<=3)
    for (; row < rend; ++row) {
        const float4* e = (const float4*)(emb + (size_t)row * D);
        float4 a = e[lane], b = e[lane + 32];
        float s = fmaf(a.x, q0.x, fmaf(a.y, q0.y, fmaf(a.z, q0.z, a.w * q0.w)));
        s = fmaf(b.x, q1.x, fmaf(b.y, q1.y, fmaf(b.z, q1.z, fmaf(b.w, q1.w, s))));
#pragma unroll
        for (int off = 16; off > 0; off >>= 1)
            s += __shfl_xor_sync(0xffffffffu, s, off);
        if (lane == 0) insert_top5(s, row, tv, ti);
    }

    // --- per-block merge of 256 per-thread lists -> block top-5 ---
#pragma unroll
    for (int j = 0; j < K; ++j) { mv[t * K + j] = tv[j]; mi[t * K + j] = ti[j]; }
    for (int sft = THREADS / 2; sft >= 1; sft >>= 1) {
        __syncthreads();
        if (t < sft) {
#pragma unroll
            for (int j = 0; j < K; ++j) { tv[j] = mv[t * K + j]; ti[j] = mi[t * K + j]; }
#pragma unroll
            for (int j = 0; j < K; ++j)
                insert_top5(mv[(t + sft) * K + j], mi[(t + sft) * K + j], tv, ti);
#pragma unroll
            for (int j = 0; j < K; ++j) { mv[t * K + j] = tv[j]; mi[t * K + j] = ti[j]; }
        }
    }
    __syncthreads();

    // --- lock-free global merge: threads 0..4 insert block candidates via
    //     atomicMax cascade. Final slots = exact global top-5 (order-independent:
    //     every displaced value is re-inserted downstream). Early-skip is safe:
    //     slots grow monotonically. ---
    if (t < K) {
        unsigned long long key = pack_key(mv[t], mi[t]);
        volatile unsigned long long* vt = (volatile unsigned long long*)g_top5;
        if (key > vt[K - 1]) {
#pragma unroll
            for (int j = 0; j < K; ++j) {
                unsigned long long old = atomicMax(&g_top5[j], key);
                if (old < key) key = old;       // carry displaced value down
                if (key == 0ull) break;         // nothing left to place
            }
        }
    }

    // --- last-block-done tail: decode 5 slots, write output, reset (tiny) ---
    if (t == 0) {
        __threadfence();                         // order my atomicMax ops before g_done
        unsigned int prev = atomicAdd(&g_done, 1u);
        s_last = (prev == (unsigned int)(gridDim.x - 1));
    }
    __syncthreads();
    if (!s_last) return;

    if (t == 0) {
        __threadfence();                         // acquire: all blocks' merges visible
#pragma unroll
        for (int j = 0; j < K; ++j) {
            unsigned long long k = atomicAdd(&g_top5[j], 0ull);   // atomic read
            unsigned int hb = (unsigned int)(k >> 32);
            unsigned int lb = (unsigned int)k;
            int idx = (int)(~lb);
            unsigned int vb = (hb & 0x80000000u) ? (hb & 0x7FFFFFFFu) : ~hb;
            out[j]     = (float)idx;             // top_idx (reference tuple order: idx first)
            out[K + j] = __uint_as_float(vb);    // top_vals
            g_top5[j] = 0ull;                    // reset for next graph replay
        }
        g_done = 0;
    }
}

extern "C" void kernel_launch(void* const* d_in, const int* in_sizes, int n_in,
                              void* d_out, int out_size) {
    const float* q   = (const float*)d_in[0];   // [1, 256]
    const float* emb = (const float*)d_in[1];   // [N, 256]
    const int n = in_sizes[1] / D;

    knn_scan<<<BLOCKS, THREADS>>>(q, emb, n, (float*)d_out);
}